// round 13
// baseline (speedup 1.0000x reference)
#include <cuda_runtime.h>
#include <cstdint>

// PatchTransformer R13: single-wave (1024 blocks x 128 thr, 8 CTA/SM cap),
// each warp owns a 64px column strip x 4 rows strided 256 apart (uniform
// patch-work balance by construction), all 12 float2 clean loads issued
// upfront (96B/thread in flight -> DRAM latency-BW product covered), per-row
// warp ballot candidate mask (no smem, no syncthreads). Exact-fp replication
// of the reference grid_sample chain (rn intrinsics block FMA contraction):
// reference gates on mask==1.0 and adv==0.0 equality.

#define S 1024
#define PS 256
#define NP 8

__global__ __launch_bounds__(128, 8)
void patch_transformer_kernel(const float* __restrict__ patches,   // [8,3,256,256]
                              const float* __restrict__ locs,      // [8,2]
                              const float* __restrict__ clean,     // [3,1024,1024]
                              float* __restrict__ out)             // [3,1024,1024]
{
    const int lane = threadIdx.x & 31;
    const int wid  = threadIdx.x >> 5;

    // Global warp task: 4096 warps = 16 column strips x 256 row-bases.
    const int g      = blockIdx.x * 4 + wid;
    const int wstrip = g & 15;
    const int hbase  = g >> 4;          // 0..255; rows hbase + 256*k
    const int bw0    = wstrip * 64;
    const int w0     = bw0 + lane * 2;

    // ---- Phase 1: issue ALL clean loads (12 x LDG.64 per thread in flight).
    float2 d[4][3];
    int pixk[4];
    #pragma unroll
    for (int k = 0; k < 4; ++k) {
        const int h = hbase + 256 * k;
        const int pix = h * S + w0;
        pixk[k] = pix;
        d[k][0] = *(const float2*)(clean + pix);
        d[k][1] = *(const float2*)(clean + pix + S * S);
        d[k][2] = *(const float2*)(clean + pix + 2 * S * S);
    }

    // Per-lane patch location preload (lanes 0..7 own one patch each).
    float plx = 0.0f, ply = 0.0f;
    if (lane < NP) {
        plx = __ldg(locs + 2 * lane + 0);
        ply = __ldg(locs + 2 * lane + 1);
    }
    const float ppx = 512.0f * plx;
    const float ppy = 512.0f * ply;

    // Normalized grid x coords (same w for all 4 rows), exact reference chain.
    float gxk[2];
    #pragma unroll
    for (int k = 0; k < 2; ++k)
        gxk[k] = __fadd_rn(__fmul_rn(__fmul_rn(__fadd_rn((float)(w0 + k), 0.5f), 2.0f),
                                     (1.0f / 1024.0f)), -1.0f);

    // x-overlap of this warp's strip with each lane's patch (row-invariant).
    const bool xhit = (lane < NP) &&
                      ((float)bw0        <= ppx + 258.0f) &&
                      ((float)(bw0 + 63) >= ppx - 2.0f);

    // ---- Phase 2: per row, ballot mask -> composite -> store.
    #pragma unroll
    for (int k = 0; k < 4; ++k) {
        const int h = hbase + 256 * k;

        // Conservative single-row candidate test. Exact sample coord
        // y == h - 512*ly to within <1e-3 px; the row can touch patch data
        // only if y in [-1,257). +-2 px margin keeps it strictly conservative.
        const bool hit = xhit &&
                         ((float)h <= ppy + 258.0f) &&
                         ((float)h >= ppy - 2.0f);
        unsigned cmask = __ballot_sync(0xFFFFFFFFu, hit) & 0xFFu;

        if (cmask) {
            const float gy = __fadd_rn(__fmul_rn(__fmul_rn(__fadd_rn((float)h, 0.5f), 2.0f),
                                                 (1.0f / 1024.0f)), -1.0f);
            do {
                const int n = __ffs(cmask) - 1;   // ascending = reference paste order
                cmask &= cmask - 1;

                const float lx = __shfl_sync(0xFFFFFFFFu, plx, n);
                const float ly = __shfl_sync(0xFFFFFFFFu, ply, n);

                // Exact reference chain (bit-for-bit); y shared by both pixels.
                const float gry = __fadd_rn(gy, -ly);
                const float y = __fmul_rn(__fadd_rn(__fmul_rn(__fadd_rn(gry, 1.0f), 1024.0f), -1.0f), 0.5f);
                const float y0f = floorf(y);
                const int iy0 = (int)y0f;
                if ((unsigned)(iy0 + 1) > 256u) continue;

                const float wy1 = __fadd_rn(y, -y0f);
                const float wy0 = __fadd_rn(1.0f, -wy1);
                const bool vy0 = (iy0 >= 0);
                const bool cy1 = (iy0 <= PS - 2);

                const float* P = patches + (size_t)n * 3 * PS * PS;
                const int rowoff = iy0 * PS;

                #pragma unroll
                for (int q = 0; q < 2; ++q) {
                    const float grx = __fadd_rn(gxk[q], -lx);
                    const float x = __fmul_rn(__fadd_rn(__fmul_rn(__fadd_rn(grx, 1.0f), 1024.0f), -1.0f), 0.5f);
                    const float x0f = floorf(x);
                    const int ix0 = (int)x0f;
                    if ((unsigned)(ix0 + 1) > 256u) continue;

                    const float wx1 = __fadd_rn(x, -x0f);
                    const float wx0 = __fadd_rn(1.0f, -wx1);

                    const float w00 = __fmul_rn(wy0, wx0);
                    const float w01 = __fmul_rn(wy0, wx1);
                    const float w10 = __fmul_rn(wy1, wx0);
                    const float w11 = __fmul_rn(wy1, wx1);

                    const bool vx0 = (ix0 >= 0);
                    // mask_w = left-associated sum of valid*weight, exactly as
                    // reference (+1 taps always frame-valid inside footprint).
                    const float msum = __fadd_rn(__fadd_rn(__fadd_rn(
                                           (vy0 && vx0) ? w00 : 0.0f,
                                           vy0 ? w01 : 0.0f),
                                           vx0 ? w10 : 0.0f),
                                           w11);
                    if (msum != 1.0f) continue;

                    const bool cx1 = (ix0 <= PS - 2);
                    const bool t00v = vy0 && vx0;
                    const bool t01v = vy0 && cx1;
                    const bool t10v = cy1 && vx0;
                    const bool t11v = cy1 && cx1;
                    if (!(t00v | t01v | t10v | t11v)) continue;

                    const int o00 = rowoff + ix0;
                    #pragma unroll
                    for (int c = 0; c < 3; ++c) {
                        const float* B = P + c * PS * PS;
                        const float t00 = t00v ? __fmul_rn(__ldg(B + o00),          w00) : 0.0f;
                        const float t01 = t01v ? __fmul_rn(__ldg(B + o00 + 1),      w01) : 0.0f;
                        const float t10 = t10v ? __fmul_rn(__ldg(B + o00 + PS),     w10) : 0.0f;
                        const float t11 = t11v ? __fmul_rn(__ldg(B + o00 + PS + 1), w11) : 0.0f;
                        const float p = __fadd_rn(__fadd_rn(__fadd_rn(t00, t01), t10), t11);
                        if (p != 0.0f) {
                            if (q == 0) d[k][c].x = p;
                            else        d[k][c].y = p;
                        }
                    }
                }
            } while (cmask);
        }

        *(float2*)(out + pixk[k])             = d[k][0];
        *(float2*)(out + pixk[k] + S * S)     = d[k][1];
        *(float2*)(out + pixk[k] + 2 * S * S) = d[k][2];
    }
}

extern "C" void kernel_launch(void* const* d_in, const int* in_sizes, int n_in,
                              void* d_out, int out_size) {
    const float* patches = (const float*)d_in[0];   // (8,3,256,256)
    const float* locs    = (const float*)d_in[1];   // (8,2)
    const float* clean   = (const float*)d_in[2];   // (3,1024,1024)
    float* out = (float*)d_out;                     // (1,3,1024,1024)

    patch_transformer_kernel<<<1024, 128>>>(patches, locs, clean, out);
}